// round 1
// baseline (speedup 1.0000x reference)
#include <cuda_runtime.h>

#define Lc 1024
#define Bc 256
#define Dc 256
#define Tc 50
#define Hc 8
#define DHc 32

// Scratch (allocation-free rule: __device__ globals)
__device__ float g_hbar[Bc*Dc];
__device__ float g_q1[Bc*Dc];
__device__ float g_qk[Bc*Hc*Dc];     // [b][h][i], includes 1/sqrt(32)
__device__ float g_w[Bc*Hc*Lc];      // [b][h][l]: scores -> softmax weights (in place)
__device__ float g_wE[Bc*Hc*Dc];     // [b][h][i]
__device__ float g_qk2[Bc*Dc];       // [b][i], includes 1/sqrt(256)

__device__ __forceinline__ unsigned long long f2ull(float x, float y) {
    unsigned long long u;
    asm("mov.b64 %0, {%1,%2};" : "=l"(u) : "f"(x), "f"(y));
    return u;
}
__device__ __forceinline__ float2 ull2f2(unsigned long long u) {
    float2 f;
    asm("mov.b64 {%0,%1}, %2;" : "=f"(f.x), "=f"(f.y) : "l"(u));
    return f;
}
__device__ __forceinline__ void fma2(unsigned long long& acc, unsigned long long a, unsigned long long b) {
    asm("fma.rn.f32x2 %0, %1, %2, %3;" : "=l"(acc) : "l"(a), "l"(b), "l"(acc));
}

// ---------------- Pass 1: hbar = mean_l ebp ----------------
__global__ void k_mean(const float* __restrict__ ebp) {
    int idx = blockIdx.x * 256 + threadIdx.x;   // b*D + d
    const float* p = ebp + idx;
    float a0 = 0.f, a1 = 0.f, a2 = 0.f, a3 = 0.f;
    #pragma unroll 2
    for (int l = 0; l < Lc; l += 4) {
        a0 += p[(l + 0) * Bc * Dc];
        a1 += p[(l + 1) * Bc * Dc];
        a2 += p[(l + 2) * Bc * Dc];
        a3 += p[(l + 3) * Bc * Dc];
    }
    g_hbar[idx] = (a0 + a1 + a2 + a3) * (1.0f / Lc);
}

// ---------------- q1 = [hbar, prev_emb, first_emb] @ Wq1 ----------------
__global__ void k_q1(const float* __restrict__ ebp, const int* __restrict__ pa,
                     const float* __restrict__ Wq1) {
    int b = blockIdx.x, t = threadIdx.x;
    __shared__ float ctx[3 * Dc];
    int aL = pa[b * Tc + (Tc - 1)];
    int a0 = pa[b * Tc];
    ctx[t]          = g_hbar[b * Dc + t];
    ctx[Dc + t]     = ebp[(size_t)aL * Bc * Dc + b * Dc + t];
    ctx[2 * Dc + t] = ebp[(size_t)a0 * Bc * Dc + b * Dc + t];
    __syncthreads();
    float s0 = 0.f, s1 = 0.f, s2 = 0.f, s3 = 0.f;
    #pragma unroll 4
    for (int i = 0; i < 3 * Dc; i += 4) {
        s0 = fmaf(ctx[i + 0], Wq1[(i + 0) * Dc + t], s0);
        s1 = fmaf(ctx[i + 1], Wq1[(i + 1) * Dc + t], s1);
        s2 = fmaf(ctx[i + 2], Wq1[(i + 2) * Dc + t], s2);
        s3 = fmaf(ctx[i + 3], Wq1[(i + 3) * Dc + t], s3);
    }
    g_q1[b * Dc + t] = (s0 + s1) + (s2 + s3);
}

// ---------------- qk[b,h,i] = sum_d q1[b,h*32+d] * Wk1[i,h*32+d] ----------------
__global__ void k_qk(const float* __restrict__ Wk1) {
    int bh = blockIdx.x;
    int b = bh >> 3, h = bh & 7;
    __shared__ float q1h[DHc];
    int t = threadIdx.x;
    if (t < DHc) q1h[t] = g_q1[b * Dc + h * DHc + t];
    __syncthreads();
    const float* wrow = Wk1 + t * Dc + h * DHc;
    float acc = 0.f;
    #pragma unroll
    for (int d = 0; d < DHc; d++) acc = fmaf(q1h[d], wrow[d], acc);
    g_qk[(b * Hc + h) * Dc + t] = acc * 0.17677669529663687f;  // 1/sqrt(32)
}

// ---------------- Pass 2: scores[l,b,h] = ebp[l,b,:] . qk[b,h,:]  (+mask) ----------------
__global__ void __launch_bounds__(256, 2) k_scores(const float* __restrict__ ebp,
                                                   const int* __restrict__ pa) {
    int b = blockIdx.x, t = threadIdx.x;
    int warp = t >> 5, lane = t & 31;
    __shared__ unsigned mbits[32];
    if (t < 32) mbits[t] = 0u;
    __syncthreads();
    if (t < Tc) {
        int a = pa[b * Tc + t];
        atomicOr(&mbits[a >> 5], 1u << (a & 31));
    }
    __syncthreads();

    // lane owns elements i = lane*8 .. lane*8+7 of every head's qk, as packed f32 pairs
    unsigned long long qkp[Hc][4];
    {
        const ulonglong2* qb = (const ulonglong2*)(g_qk + b * Hc * Dc);
        #pragma unroll
        for (int h = 0; h < Hc; h++) {
            ulonglong2 u0 = qb[h * (Dc / 4) + lane * 2];
            ulonglong2 u1 = qb[h * (Dc / 4) + lane * 2 + 1];
            qkp[h][0] = u0.x; qkp[h][1] = u0.y; qkp[h][2] = u1.x; qkp[h][3] = u1.y;
        }
    }

    for (int l = warp; l < Lc; l += 8) {
        const ulonglong2* er = (const ulonglong2*)(ebp + ((size_t)l * Bc + b) * Dc);
        ulonglong2 e0 = er[lane * 2];
        ulonglong2 e1 = er[lane * 2 + 1];
        unsigned long long ep[4] = {e0.x, e0.y, e1.x, e1.y};
        float sc[Hc];
        #pragma unroll
        for (int h = 0; h < Hc; h++) {
            unsigned long long acc = 0ull;  // packed (0,0)
            #pragma unroll
            for (int e = 0; e < 4; e++) fma2(acc, ep[e], qkp[h][e]);
            float2 f = ull2f2(acc);
            sc[h] = f.x + f.y;
        }
        #pragma unroll
        for (int h = 0; h < Hc; h++) {
            #pragma unroll
            for (int o = 16; o > 0; o >>= 1)
                sc[h] += __shfl_xor_sync(0xffffffffu, sc[h], o);
        }
        if (lane == 0) {
            bool m = (mbits[l >> 5] >> (l & 31)) & 1u;
            #pragma unroll
            for (int h = 0; h < Hc; h++)
                g_w[(b * Hc + h) * Lc + l] = m ? -1e30f : sc[h];
        }
    }
}

// ---------------- softmax over l for each (b,h), in place ----------------
__global__ void k_softmax_w() {
    int bh = blockIdx.x, t = threadIdx.x;
    float* row = g_w + bh * Lc;
    __shared__ float red[256];
    float v[4];
    float mx = -1e30f;
    #pragma unroll
    for (int i = 0; i < 4; i++) { v[i] = row[t + i * 256]; mx = fmaxf(mx, v[i]); }
    red[t] = mx; __syncthreads();
    for (int s = 128; s > 0; s >>= 1) { if (t < s) red[t] = fmaxf(red[t], red[t + s]); __syncthreads(); }
    mx = red[0]; __syncthreads();
    float sm = 0.f;
    #pragma unroll
    for (int i = 0; i < 4; i++) { v[i] = __expf(v[i] - mx); sm += v[i]; }
    red[t] = sm; __syncthreads();
    for (int s = 128; s > 0; s >>= 1) { if (t < s) red[t] += red[t + s]; __syncthreads(); }
    float inv = 1.0f / red[0];
    #pragma unroll
    for (int i = 0; i < 4; i++) row[t + i * 256] = v[i] * inv;
}

// ---------------- Pass 3: wE[b,h,i] = sum_l w[l,b,h] * ebp[l,b,i] ----------------
__global__ void __launch_bounds__(256, 2) k_wE(const float* __restrict__ ebp) {
    int b = blockIdx.x, t = threadIdx.x;  // t = column i
    __shared__ float2 ws[64][4];          // [l-sub][head-pair]
    unsigned long long acc[4] = {0ull, 0ull, 0ull, 0ull};
    const float* col = ebp + b * Dc + t;
    for (int l0 = 0; l0 < Lc; l0 += 64) {
        __syncthreads();
        #pragma unroll
        for (int k = 0; k < 2; k++) {
            int idx = t + k * 256;   // 0..511
            int h = idx >> 6, ll = idx & 63;
            float wv = g_w[(b * Hc + h) * Lc + l0 + ll];
            ((float*)&ws[ll][h >> 1])[h & 1] = wv;
        }
        __syncthreads();
        #pragma unroll 8
        for (int ll = 0; ll < 64; ll++) {
            float e = col[(size_t)(l0 + ll) * Bc * Dc];
            unsigned long long ee = f2ull(e, e);
            const ulonglong2* wsr = (const ulonglong2*)&ws[ll][0];
            ulonglong2 w01 = wsr[0], w23 = wsr[1];
            fma2(acc[0], w01.x, ee);
            fma2(acc[1], w01.y, ee);
            fma2(acc[2], w23.x, ee);
            fma2(acc[3], w23.y, ee);
        }
    }
    #pragma unroll
    for (int hp = 0; hp < 4; hp++) {
        float2 f = ull2f2(acc[hp]);
        g_wE[(b * Hc + 2 * hp) * Dc + t]     = f.x;
        g_wE[(b * Hc + 2 * hp + 1) * Dc + t] = f.y;
    }
}

// ---------------- fold chain: head_out -> context2 -> q2 -> qk2 (per b) ----------------
__global__ void k_fold(const float* __restrict__ Wv1, const float* __restrict__ Wo1,
                       const float* __restrict__ Wq2, const float* __restrict__ Wk2) {
    int b = blockIdx.x, t = threadIdx.x;
    __shared__ float wEs[Hc * Dc];   // 8KB
    __shared__ float hos[Hc * DHc];  // 1KB
    __shared__ float c2s[Dc];
    __shared__ float q2s[Dc];
    #pragma unroll
    for (int k = 0; k < Hc; k++) wEs[t + k * 256] = g_wE[b * Hc * Dc + t + k * 256];
    __syncthreads();
    {   // head_out[h,d], output index j = t = h*32+d
        const float* wsrc = wEs + (t >> 5) * Dc;
        float s0 = 0.f, s1 = 0.f;
        #pragma unroll 4
        for (int i = 0; i < Dc; i += 2) {
            s0 = fmaf(wsrc[i],     Wv1[(i)     * Dc + t], s0);
            s1 = fmaf(wsrc[i + 1], Wv1[(i + 1) * Dc + t], s1);
        }
        hos[t] = s0 + s1;
    }
    __syncthreads();
    {   // context2[e] = sum_{h,d} hos[h*32+d] * Wo1[(h*32+d)*D + e]
        float s0 = 0.f, s1 = 0.f;
        #pragma unroll 4
        for (int k = 0; k < Hc * DHc; k += 2) {
            s0 = fmaf(hos[k],     Wo1[(k)     * Dc + t], s0);
            s1 = fmaf(hos[k + 1], Wo1[(k + 1) * Dc + t], s1);
        }
        c2s[t] = s0 + s1;
    }
    __syncthreads();
    {   // q2[j]
        float s0 = 0.f, s1 = 0.f;
        #pragma unroll 4
        for (int e = 0; e < Dc; e += 2) {
            s0 = fmaf(c2s[e],     Wq2[(e)     * Dc + t], s0);
            s1 = fmaf(c2s[e + 1], Wq2[(e + 1) * Dc + t], s1);
        }
        q2s[t] = s0 + s1;
    }
    __syncthreads();
    {   // qk2[i] = (1/16) sum_j Wk2[i,j] * q2[j]
        const float* wr = Wk2 + t * Dc;
        float s0 = 0.f, s1 = 0.f;
        #pragma unroll 4
        for (int j = 0; j < Dc; j += 2) {
            s0 = fmaf(wr[j],     q2s[j],     s0);
            s1 = fmaf(wr[j + 1], q2s[j + 1], s1);
        }
        g_qk2[b * Dc + t] = (s0 + s1) * (1.0f / 16.0f);  // 1/sqrt(256)
    }
}

// ---------------- Pass 4: fs -> tanh*10 + mask -> softmax over l -> out ----------------
__global__ void __launch_bounds__(256, 2) k_final(const float* __restrict__ ebp,
                                                  const int* __restrict__ pa,
                                                  float* __restrict__ out) {
    int b = blockIdx.x, t = threadIdx.x;
    int warp = t >> 5, lane = t & 31;
    __shared__ unsigned mbits[32];
    __shared__ float lps[Lc];
    __shared__ float red[256];
    if (t < 32) mbits[t] = 0u;
    __syncthreads();
    if (t < Tc) {
        int a = pa[b * Tc + t];
        atomicOr(&mbits[a >> 5], 1u << (a & 31));
    }
    __syncthreads();
    unsigned long long qp[4];
    {
        const ulonglong2* qb = (const ulonglong2*)(g_qk2 + b * Dc);
        ulonglong2 u0 = qb[lane * 2], u1 = qb[lane * 2 + 1];
        qp[0] = u0.x; qp[1] = u0.y; qp[2] = u1.x; qp[3] = u1.y;
    }
    for (int l = warp; l < Lc; l += 8) {
        const ulonglong2* er = (const ulonglong2*)(ebp + ((size_t)l * Bc + b) * Dc);
        ulonglong2 e0 = er[lane * 2], e1 = er[lane * 2 + 1];
        unsigned long long acc = 0ull;
        fma2(acc, e0.x, qp[0]);
        fma2(acc, e0.y, qp[1]);
        fma2(acc, e1.x, qp[2]);
        fma2(acc, e1.y, qp[3]);
        float2 f = ull2f2(acc);
        float s = f.x + f.y;
        #pragma unroll
        for (int o = 16; o > 0; o >>= 1) s += __shfl_xor_sync(0xffffffffu, s, o);
        if (lane == 0) {
            bool m = (mbits[l >> 5] >> (l & 31)) & 1u;
            lps[l] = m ? -1e30f : tanhf(s) * 10.0f;
        }
    }
    __syncthreads();
    float v[4];
    float mx = -1e30f;
    #pragma unroll
    for (int i = 0; i < 4; i++) { v[i] = lps[t + i * 256]; mx = fmaxf(mx, v[i]); }
    red[t] = mx; __syncthreads();
    for (int s = 128; s > 0; s >>= 1) { if (t < s) red[t] = fmaxf(red[t], red[t + s]); __syncthreads(); }
    mx = red[0]; __syncthreads();
    float sm = 0.f;
    #pragma unroll
    for (int i = 0; i < 4; i++) { v[i] = __expf(v[i] - mx); sm += v[i]; }
    red[t] = sm; __syncthreads();
    for (int s = 128; s > 0; s >>= 1) { if (t < s) red[t] += red[t + s]; __syncthreads(); }
    float inv = 1.0f / red[0];
    #pragma unroll
    for (int i = 0; i < 4; i++)
        out[(size_t)(t + i * 256) * Bc + b] = v[i] * inv;
}

extern "C" void kernel_launch(void* const* d_in, const int* in_sizes, int n_in,
                              void* d_out, int out_size) {
    const float* ebp = (const float*)d_in[0];
    const int*   pa  = (const int*)d_in[1];
    const float* Wq1 = (const float*)d_in[2];
    const float* Wk1 = (const float*)d_in[3];
    const float* Wv1 = (const float*)d_in[4];
    const float* Wo1 = (const float*)d_in[5];
    const float* Wq2 = (const float*)d_in[6];
    const float* Wk2 = (const float*)d_in[7];
    float* out = (float*)d_out;

    k_mean     <<<(Bc * Dc) / 256, 256>>>(ebp);
    k_q1       <<<Bc, 256>>>(ebp, pa, Wq1);
    k_qk       <<<Bc * Hc, 256>>>(Wk1);
    k_scores   <<<Bc, 256>>>(ebp, pa);
    k_softmax_w<<<Bc * Hc, 256>>>();
    k_wE       <<<Bc, 256>>>(ebp);
    k_fold     <<<Bc, 256>>>(Wv1, Wo1, Wq2, Wk2);
    k_final    <<<Bc, 256>>>(ebp, pa, out);
}

// round 2
// speedup vs baseline: 1.1785x; 1.1785x over previous
#include <cuda_runtime.h>

#define Lc 1024
#define Bc 256
#define Dc 256
#define Tc 50
#define Hc 8
#define DHc 32

#define MEAN_CH 8   // L-chunks for mean pass
#define WE_CH 4     // L-chunks for wE pass

// Scratch (allocation-free rule: __device__ globals)
__device__ float g_hbar_part[MEAN_CH][Bc*Dc];   // partial sums over l-chunks
__device__ float g_q1[Bc*Dc];
__device__ float g_qk[Bc*Hc*Dc];                // [b][h][i], includes 1/sqrt(32)
__device__ float g_w[Bc*Hc*Lc];                 // [b][h][l]
__device__ float g_wE_part[WE_CH][Bc*Hc*Dc];    // partial [b][h][i]
__device__ float g_qk2[Bc*Dc];                  // [b][i], includes 1/sqrt(256)
__device__ float g_fs[Bc*Lc];                   // [b][l] masked tanh scores

__device__ __forceinline__ unsigned long long f2ull(float x, float y) {
    unsigned long long u;
    asm("mov.b64 %0, {%1,%2};" : "=l"(u) : "f"(x), "f"(y));
    return u;
}
__device__ __forceinline__ float2 ull2f2(unsigned long long u) {
    float2 f;
    asm("mov.b64 {%0,%1}, %2;" : "=f"(f.x), "=f"(f.y) : "l"(u));
    return f;
}
__device__ __forceinline__ void fma2(unsigned long long& acc, unsigned long long a, unsigned long long b) {
    asm("fma.rn.f32x2 %0, %1, %2, %3;" : "=l"(acc) : "l"(a), "l"(b), "l"(acc));
}

// ---------------- Pass 1: partial sums for hbar ----------------
// grid (128, MEAN_CH), block 128. Each thread owns a float4 column group,
// sums over L/MEAN_CH rows.
__global__ void k_mean_part(const float* __restrict__ ebp) {
    int cg = blockIdx.x * 128 + threadIdx.x;            // float4 column group 0..16383
    int l0 = blockIdx.y * (Lc / MEAN_CH);
    const float4* p = (const float4*)ebp + (size_t)l0 * (Bc * Dc / 4) + cg;
    float4 a0 = {0,0,0,0}, a1 = {0,0,0,0}, a2 = {0,0,0,0}, a3 = {0,0,0,0};
    #pragma unroll 4
    for (int l = 0; l < Lc / MEAN_CH; l += 4) {
        float4 v0 = p[(size_t)(l + 0) * (Bc * Dc / 4)];
        float4 v1 = p[(size_t)(l + 1) * (Bc * Dc / 4)];
        float4 v2 = p[(size_t)(l + 2) * (Bc * Dc / 4)];
        float4 v3 = p[(size_t)(l + 3) * (Bc * Dc / 4)];
        a0.x += v0.x; a0.y += v0.y; a0.z += v0.z; a0.w += v0.w;
        a1.x += v1.x; a1.y += v1.y; a1.z += v1.z; a1.w += v1.w;
        a2.x += v2.x; a2.y += v2.y; a2.z += v2.z; a2.w += v2.w;
        a3.x += v3.x; a3.y += v3.y; a3.z += v3.z; a3.w += v3.w;
    }
    float4 r;
    r.x = (a0.x + a1.x) + (a2.x + a3.x);
    r.y = (a0.y + a1.y) + (a2.y + a3.y);
    r.z = (a0.z + a1.z) + (a2.z + a3.z);
    r.w = (a0.w + a1.w) + (a2.w + a3.w);
    ((float4*)g_hbar_part[blockIdx.y])[cg] = r;
}

// ---------------- q1 = [hbar, prev_emb, first_emb] @ Wq1 ----------------
__global__ void k_q1(const float* __restrict__ ebp, const int* __restrict__ pa,
                     const float* __restrict__ Wq1) {
    int b = blockIdx.x, t = threadIdx.x;
    __shared__ float ctx[3 * Dc];
    int aL = pa[b * Tc + (Tc - 1)];
    int a0 = pa[b * Tc];
    float hs = 0.f;
    #pragma unroll
    for (int c = 0; c < MEAN_CH; c++) hs += g_hbar_part[c][b * Dc + t];
    ctx[t]          = hs * (1.0f / Lc);
    ctx[Dc + t]     = ebp[(size_t)aL * Bc * Dc + b * Dc + t];
    ctx[2 * Dc + t] = ebp[(size_t)a0 * Bc * Dc + b * Dc + t];
    __syncthreads();
    float s0 = 0.f, s1 = 0.f, s2 = 0.f, s3 = 0.f;
    #pragma unroll 4
    for (int i = 0; i < 3 * Dc; i += 4) {
        s0 = fmaf(ctx[i + 0], Wq1[(i + 0) * Dc + t], s0);
        s1 = fmaf(ctx[i + 1], Wq1[(i + 1) * Dc + t], s1);
        s2 = fmaf(ctx[i + 2], Wq1[(i + 2) * Dc + t], s2);
        s3 = fmaf(ctx[i + 3], Wq1[(i + 3) * Dc + t], s3);
    }
    g_q1[b * Dc + t] = (s0 + s1) + (s2 + s3);
}

// ---------------- qk[b,h,i] = sum_d q1[b,h*32+d] * Wk1[i,h*32+d] ----------------
__global__ void k_qk(const float* __restrict__ Wk1) {
    int bh = blockIdx.x;
    int b = bh >> 3, h = bh & 7;
    __shared__ float q1h[DHc];
    int t = threadIdx.x;
    if (t < DHc) q1h[t] = g_q1[b * Dc + h * DHc + t];
    __syncthreads();
    const float* wrow = Wk1 + t * Dc + h * DHc;
    float acc = 0.f;
    #pragma unroll
    for (int d = 0; d < DHc; d++) acc = fmaf(q1h[d], wrow[d], acc);
    g_qk[(b * Hc + h) * Dc + t] = acc * 0.17677669529663687f;  // 1/sqrt(32)
}

// ---------------- Pass 2: scores[l,b,h] = ebp[l,b,:] . qk[b,h,:]  (+mask) ----------------
// grid (Bc, 4): each block handles a 256-long l-chunk for one b.
__global__ void __launch_bounds__(256, 2) k_scores(const float* __restrict__ ebp,
                                                   const int* __restrict__ pa) {
    int b = blockIdx.x, t = threadIdx.x;
    int warp = t >> 5, lane = t & 31;
    int l0 = blockIdx.y * 256;
    __shared__ unsigned mbits[32];
    if (t < 32) mbits[t] = 0u;
    __syncthreads();
    if (t < Tc) {
        int a = pa[b * Tc + t];
        atomicOr(&mbits[a >> 5], 1u << (a & 31));
    }
    __syncthreads();

    // lane owns elements i = lane*8 .. lane*8+7 of every head's qk, as packed f32 pairs
    unsigned long long qkp[Hc][4];
    {
        const ulonglong2* qb = (const ulonglong2*)(g_qk + b * Hc * Dc);
        #pragma unroll
        for (int h = 0; h < Hc; h++) {
            ulonglong2 u0 = qb[h * (Dc / 4) + lane * 2];
            ulonglong2 u1 = qb[h * (Dc / 4) + lane * 2 + 1];
            qkp[h][0] = u0.x; qkp[h][1] = u0.y; qkp[h][2] = u1.x; qkp[h][3] = u1.y;
        }
    }

    for (int l = l0 + warp; l < l0 + 256; l += 8) {
        const ulonglong2* er = (const ulonglong2*)(ebp + ((size_t)l * Bc + b) * Dc);
        ulonglong2 e0 = er[lane * 2];
        ulonglong2 e1 = er[lane * 2 + 1];
        unsigned long long ep[4] = {e0.x, e0.y, e1.x, e1.y};
        float sc[Hc];
        #pragma unroll
        for (int h = 0; h < Hc; h++) {
            unsigned long long acc = 0ull;
            #pragma unroll
            for (int e = 0; e < 4; e++) fma2(acc, ep[e], qkp[h][e]);
            float2 f = ull2f2(acc);
            sc[h] = f.x + f.y;
        }
        #pragma unroll
        for (int h = 0; h < Hc; h++) {
            #pragma unroll
            for (int o = 16; o > 0; o >>= 1)
                sc[h] += __shfl_xor_sync(0xffffffffu, sc[h], o);
        }
        if (lane == 0) {
            bool m = (mbits[l >> 5] >> (l & 31)) & 1u;
            #pragma unroll
            for (int h = 0; h < Hc; h++)
                g_w[(b * Hc + h) * Lc + l] = m ? -1e30f : sc[h];
        }
    }
}

// ---------------- softmax over l for each (b,h), in place ----------------
__global__ void k_softmax_w() {
    int bh = blockIdx.x, t = threadIdx.x;
    float* row = g_w + bh * Lc;
    __shared__ float red[256];
    float v[4];
    float mx = -1e30f;
    #pragma unroll
    for (int i = 0; i < 4; i++) { v[i] = row[t + i * 256]; mx = fmaxf(mx, v[i]); }
    red[t] = mx; __syncthreads();
    for (int s = 128; s > 0; s >>= 1) { if (t < s) red[t] = fmaxf(red[t], red[t + s]); __syncthreads(); }
    mx = red[0]; __syncthreads();
    float sm = 0.f;
    #pragma unroll
    for (int i = 0; i < 4; i++) { v[i] = __expf(v[i] - mx); sm += v[i]; }
    red[t] = sm; __syncthreads();
    for (int s = 128; s > 0; s >>= 1) { if (t < s) red[t] += red[t + s]; __syncthreads(); }
    float inv = 1.0f / red[0];
    #pragma unroll
    for (int i = 0; i < 4; i++) row[t + i * 256] = v[i] * inv;
}

// ---------------- Pass 3 (partial): wE_part[c][b,h,i] = sum_{l in chunk} w[l,b,h]*ebp[l,b,i] ----------------
// grid (Bc, WE_CH), block 256; t = column i.
__global__ void __launch_bounds__(256, 2) k_wE_part(const float* __restrict__ ebp) {
    int b = blockIdx.x, t = threadIdx.x;
    int cy = blockIdx.y;
    int lbase = cy * (Lc / WE_CH);
    __shared__ float2 ws[64][4];          // [l-sub][head-pair]
    unsigned long long acc[4] = {0ull, 0ull, 0ull, 0ull};
    const float* col = ebp + b * Dc + t;
    for (int l0 = lbase; l0 < lbase + Lc / WE_CH; l0 += 64) {
        __syncthreads();
        #pragma unroll
        for (int k = 0; k < 2; k++) {
            int idx = t + k * 256;   // 0..511
            int h = idx >> 6, ll = idx & 63;
            float wv = g_w[(b * Hc + h) * Lc + l0 + ll];
            ((float*)&ws[ll][h >> 1])[h & 1] = wv;
        }
        __syncthreads();
        #pragma unroll 8
        for (int ll = 0; ll < 64; ll++) {
            float e = col[(size_t)(l0 + ll) * Bc * Dc];
            unsigned long long ee = f2ull(e, e);
            const ulonglong2* wsr = (const ulonglong2*)&ws[ll][0];
            ulonglong2 w01 = wsr[0], w23 = wsr[1];
            fma2(acc[0], w01.x, ee);
            fma2(acc[1], w01.y, ee);
            fma2(acc[2], w23.x, ee);
            fma2(acc[3], w23.y, ee);
        }
    }
    #pragma unroll
    for (int hp = 0; hp < 4; hp++) {
        float2 f = ull2f2(acc[hp]);
        g_wE_part[cy][(b * Hc + 2 * hp) * Dc + t]     = f.x;
        g_wE_part[cy][(b * Hc + 2 * hp + 1) * Dc + t] = f.y;
    }
}

// ---------------- fold chain: head_out -> context2 -> q2 -> qk2 (per b) ----------------
__global__ void k_fold(const float* __restrict__ Wv1, const float* __restrict__ Wo1,
                       const float* __restrict__ Wq2, const float* __restrict__ Wk2) {
    int b = blockIdx.x, t = threadIdx.x;
    __shared__ float wEs[Hc * Dc];   // 8KB
    __shared__ float hos[Hc * DHc];  // 1KB
    __shared__ float c2s[Dc];
    __shared__ float q2s[Dc];
    #pragma unroll
    for (int k = 0; k < Hc; k++) {
        float s = 0.f;
        #pragma unroll
        for (int c = 0; c < WE_CH; c++) s += g_wE_part[c][b * Hc * Dc + t + k * 256];
        wEs[t + k * 256] = s;
    }
    __syncthreads();
    {   // head_out[h,d], output index j = t = h*32+d
        const float* wsrc = wEs + (t >> 5) * Dc;
        float s0 = 0.f, s1 = 0.f;
        #pragma unroll 4
        for (int i = 0; i < Dc; i += 2) {
            s0 = fmaf(wsrc[i],     Wv1[(i)     * Dc + t], s0);
            s1 = fmaf(wsrc[i + 1], Wv1[(i + 1) * Dc + t], s1);
        }
        hos[t] = s0 + s1;
    }
    __syncthreads();
    {   // context2[e]
        float s0 = 0.f, s1 = 0.f;
        #pragma unroll 4
        for (int k = 0; k < Hc * DHc; k += 2) {
            s0 = fmaf(hos[k],     Wo1[(k)     * Dc + t], s0);
            s1 = fmaf(hos[k + 1], Wo1[(k + 1) * Dc + t], s1);
        }
        c2s[t] = s0 + s1;
    }
    __syncthreads();
    {   // q2[j]
        float s0 = 0.f, s1 = 0.f;
        #pragma unroll 4
        for (int e = 0; e < Dc; e += 2) {
            s0 = fmaf(c2s[e],     Wq2[(e)     * Dc + t], s0);
            s1 = fmaf(c2s[e + 1], Wq2[(e + 1) * Dc + t], s1);
        }
        q2s[t] = s0 + s1;
    }
    __syncthreads();
    {   // qk2[i] = (1/16) sum_j Wk2[i,j] * q2[j]
        const float* wr = Wk2 + t * Dc;
        float s0 = 0.f, s1 = 0.f;
        #pragma unroll 4
        for (int j = 0; j < Dc; j += 2) {
            s0 = fmaf(wr[j],     q2s[j],     s0);
            s1 = fmaf(wr[j + 1], q2s[j + 1], s1);
        }
        g_qk2[b * Dc + t] = (s0 + s1) * (1.0f / 16.0f);
    }
}

// ---------------- Pass 4a: fs -> tanh*10 + mask -> g_fs[b][l] ----------------
// grid (Bc, 4)
__global__ void __launch_bounds__(256, 2) k_fs(const float* __restrict__ ebp,
                                               const int* __restrict__ pa) {
    int b = blockIdx.x, t = threadIdx.x;
    int warp = t >> 5, lane = t & 31;
    int l0 = blockIdx.y * 256;
    __shared__ unsigned mbits[32];
    if (t < 32) mbits[t] = 0u;
    __syncthreads();
    if (t < Tc) {
        int a = pa[b * Tc + t];
        atomicOr(&mbits[a >> 5], 1u << (a & 31));
    }
    __syncthreads();
    unsigned long long qp[4];
    {
        const ulonglong2* qb = (const ulonglong2*)(g_qk2 + b * Dc);
        ulonglong2 u0 = qb[lane * 2], u1 = qb[lane * 2 + 1];
        qp[0] = u0.x; qp[1] = u0.y; qp[2] = u1.x; qp[3] = u1.y;
    }
    for (int l = l0 + warp; l < l0 + 256; l += 8) {
        const ulonglong2* er = (const ulonglong2*)(ebp + ((size_t)l * Bc + b) * Dc);
        ulonglong2 e0 = er[lane * 2], e1 = er[lane * 2 + 1];
        unsigned long long acc = 0ull;
        fma2(acc, e0.x, qp[0]);
        fma2(acc, e0.y, qp[1]);
        fma2(acc, e1.x, qp[2]);
        fma2(acc, e1.y, qp[3]);
        float2 f = ull2f2(acc);
        float s = f.x + f.y;
        #pragma unroll
        for (int o = 16; o > 0; o >>= 1) s += __shfl_xor_sync(0xffffffffu, s, o);
        if (lane == 0) {
            bool m = (mbits[l >> 5] >> (l & 31)) & 1u;
            g_fs[b * Lc + l] = m ? -1e30f : tanhf(s) * 10.0f;
        }
    }
}

// ---------------- Pass 4b: per-b softmax over l, transposed store ----------------
// grid Bc, block 1024.
__global__ void k_out(float* __restrict__ out) {
    int b = blockIdx.x, t = threadIdx.x;
    int warp = t >> 5, lane = t & 31;
    __shared__ float red[32];
    float v = g_fs[b * Lc + t];
    float mx = v;
    #pragma unroll
    for (int o = 16; o > 0; o >>= 1) mx = fmaxf(mx, __shfl_xor_sync(0xffffffffu, mx, o));
    if (lane == 0) red[warp] = mx;
    __syncthreads();
    if (t < 32) {
        float m = red[t];
        #pragma unroll
        for (int o = 16; o > 0; o >>= 1) m = fmaxf(m, __shfl_xor_sync(0xffffffffu, m, o));
        red[t] = m;
    }
    __syncthreads();
    mx = red[0];
    __syncthreads();
    float e = __expf(v - mx);
    float sm = e;
    #pragma unroll
    for (int o = 16; o > 0; o >>= 1) sm += __shfl_xor_sync(0xffffffffu, sm, o);
    if (lane == 0) red[warp] = sm;
    __syncthreads();
    if (t < 32) {
        float s = red[t];
        #pragma unroll
        for (int o = 16; o > 0; o >>= 1) s += __shfl_xor_sync(0xffffffffu, s, o);
        red[t] = s;
    }
    __syncthreads();
    out[(size_t)t * Bc + b] = e * (1.0f / red[0]);
}

extern "C" void kernel_launch(void* const* d_in, const int* in_sizes, int n_in,
                              void* d_out, int out_size) {
    const float* ebp = (const float*)d_in[0];
    const int*   pa  = (const int*)d_in[1];
    const float* Wq1 = (const float*)d_in[2];
    const float* Wk1 = (const float*)d_in[3];
    const float* Wv1 = (const float*)d_in[4];
    const float* Wo1 = (const float*)d_in[5];
    const float* Wq2 = (const float*)d_in[6];
    const float* Wk2 = (const float*)d_in[7];
    float* out = (float*)d_out;

    dim3 gm(128, MEAN_CH);
    k_mean_part<<<gm, 128>>>(ebp);
    k_q1       <<<Bc, 256>>>(ebp, pa, Wq1);
    k_qk       <<<Bc * Hc, 256>>>(Wk1);
    dim3 gs(Bc, 4);
    k_scores   <<<gs, 256>>>(ebp, pa);
    k_softmax_w<<<Bc * Hc, 256>>>();
    dim3 gw(Bc, WE_CH);
    k_wE_part  <<<gw, 256>>>(ebp);
    k_fold     <<<Bc, 256>>>(Wv1, Wo1, Wq2, Wk2);
    k_fs       <<<gs, 256>>>(ebp, pa);
    k_out      <<<Bc, 1024>>>(out);
}

// round 3
// speedup vs baseline: 1.4529x; 1.2329x over previous
#include <cuda_runtime.h>

#define Lc 1024
#define Bc 256
#define Dc 256
#define Tc 50
#define Hc 8
#define DHc 32

#define MEAN_CH 16  // L-chunks for mean pass
#define WE_CH 4     // L-chunks for wE pass

// Scratch (allocation-free rule: __device__ globals)
__device__ float g_hbar_part[MEAN_CH][Bc*Dc];
__device__ float g_q1[Bc*Dc];
__device__ float g_qk[Bc*Hc*Dc];                // [b][h][i], includes 1/sqrt(32)
__device__ float g_w[Bc*Hc*Lc];                 // [b][h][l]
__device__ float g_wE_part[WE_CH][Bc*Hc*Dc];    // partial [b][h][i]
__device__ float g_qk2[Bc*Dc];                  // [b][i], includes 1/sqrt(256)
__device__ float g_fs[Bc*Lc];                   // [b][l]

__device__ __forceinline__ unsigned long long f2ull(float x, float y) {
    unsigned long long u;
    asm("mov.b64 %0, {%1,%2};" : "=l"(u) : "f"(x), "f"(y));
    return u;
}
__device__ __forceinline__ float2 ull2f2(unsigned long long u) {
    float2 f;
    asm("mov.b64 {%0,%1}, %2;" : "=f"(f.x), "=f"(f.y) : "l"(u));
    return f;
}
__device__ __forceinline__ void fma2(unsigned long long& acc, unsigned long long a, unsigned long long b) {
    asm("fma.rn.f32x2 %0, %1, %2, %3;" : "=l"(acc) : "l"(a), "l"(b), "l"(acc));
}

// 8-value fold reduction: input sc[8] per-lane head partials, output: full sum.
// Result: lanes with lane%4==0 hold head (lane>>2). 9 shuffles.
__device__ __forceinline__ float fold8(const float sc[8], int lane) {
    bool hi16 = (lane & 16) != 0;
    float n[4];
    #pragma unroll
    for (int k = 0; k < 4; k++) {
        float give = hi16 ? sc[k] : sc[4 + k];
        float keep = hi16 ? sc[4 + k] : sc[k];
        n[k] = keep + __shfl_xor_sync(0xffffffffu, give, 16);
    }
    bool hi8 = (lane & 8) != 0;
    float m[2];
    #pragma unroll
    for (int j = 0; j < 2; j++) {
        float give = hi8 ? n[j] : n[2 + j];
        float keep = hi8 ? n[2 + j] : n[j];
        m[j] = keep + __shfl_xor_sync(0xffffffffu, give, 8);
    }
    bool hi4 = (lane & 4) != 0;
    float give = hi4 ? m[0] : m[1];
    float keep = hi4 ? m[1] : m[0];
    float v = keep + __shfl_xor_sync(0xffffffffu, give, 4);
    v += __shfl_xor_sync(0xffffffffu, v, 1);
    v += __shfl_xor_sync(0xffffffffu, v, 2);
    return v;
}

// 4-value fold: input r[4] per-lane row partials. Lanes with lane%8==0 hold row (lane>>3).
__device__ __forceinline__ float fold4(const float r[4], int lane) {
    bool hi16 = (lane & 16) != 0;
    float n[2];
    #pragma unroll
    for (int j = 0; j < 2; j++) {
        float give = hi16 ? r[j] : r[2 + j];
        float keep = hi16 ? r[2 + j] : r[j];
        n[j] = keep + __shfl_xor_sync(0xffffffffu, give, 16);
    }
    bool hi8 = (lane & 8) != 0;
    float give = hi8 ? n[0] : n[1];
    float keep = hi8 ? n[1] : n[0];
    float v = keep + __shfl_xor_sync(0xffffffffu, give, 8);
    v += __shfl_xor_sync(0xffffffffu, v, 4);
    v += __shfl_xor_sync(0xffffffffu, v, 2);
    v += __shfl_xor_sync(0xffffffffu, v, 1);
    return v;
}

// ---------------- Pass 1: partial sums for hbar. grid (64, MEAN_CH), block 256 ----------------
__global__ void k_mean_part(const float* __restrict__ ebp) {
    int cg = blockIdx.x * 256 + threadIdx.x;           // float4 col group 0..16383
    int l0 = blockIdx.y * (Lc / MEAN_CH);              // 64-row chunk
    const float4* p = (const float4*)ebp + (size_t)l0 * (Bc * Dc / 4) + cg;
    float4 a0 = {0,0,0,0}, a1 = {0,0,0,0}, a2 = {0,0,0,0}, a3 = {0,0,0,0};
    #pragma unroll 2
    for (int l = 0; l < Lc / MEAN_CH; l += 8) {
        float4 v0 = p[(size_t)(l + 0) * (Bc * Dc / 4)];
        float4 v1 = p[(size_t)(l + 1) * (Bc * Dc / 4)];
        float4 v2 = p[(size_t)(l + 2) * (Bc * Dc / 4)];
        float4 v3 = p[(size_t)(l + 3) * (Bc * Dc / 4)];
        float4 v4 = p[(size_t)(l + 4) * (Bc * Dc / 4)];
        float4 v5 = p[(size_t)(l + 5) * (Bc * Dc / 4)];
        float4 v6 = p[(size_t)(l + 6) * (Bc * Dc / 4)];
        float4 v7 = p[(size_t)(l + 7) * (Bc * Dc / 4)];
        a0.x += v0.x; a0.y += v0.y; a0.z += v0.z; a0.w += v0.w;
        a1.x += v1.x; a1.y += v1.y; a1.z += v1.z; a1.w += v1.w;
        a2.x += v2.x; a2.y += v2.y; a2.z += v2.z; a2.w += v2.w;
        a3.x += v3.x; a3.y += v3.y; a3.z += v3.z; a3.w += v3.w;
        a0.x += v4.x; a0.y += v4.y; a0.z += v4.z; a0.w += v4.w;
        a1.x += v5.x; a1.y += v5.y; a1.z += v5.z; a1.w += v5.w;
        a2.x += v6.x; a2.y += v6.y; a2.z += v6.z; a2.w += v6.w;
        a3.x += v7.x; a3.y += v7.y; a3.z += v7.z; a3.w += v7.w;
    }
    float4 r;
    r.x = (a0.x + a1.x) + (a2.x + a3.x);
    r.y = (a0.y + a1.y) + (a2.y + a3.y);
    r.z = (a0.z + a1.z) + (a2.z + a3.z);
    r.w = (a0.w + a1.w) + (a2.w + a3.w);
    ((float4*)g_hbar_part[blockIdx.y])[cg] = r;
}

// ---------------- q1 = [hbar, prev_emb, first_emb] @ Wq1 ----------------
__global__ void k_q1(const float* __restrict__ ebp, const int* __restrict__ pa,
                     const float* __restrict__ Wq1) {
    int b = blockIdx.x, t = threadIdx.x;
    __shared__ float ctx[3 * Dc];
    int aL = pa[b * Tc + (Tc - 1)];
    int a0 = pa[b * Tc];
    float hs = 0.f;
    #pragma unroll
    for (int c = 0; c < MEAN_CH; c++) hs += g_hbar_part[c][b * Dc + t];
    ctx[t]          = hs * (1.0f / Lc);
    ctx[Dc + t]     = ebp[(size_t)aL * Bc * Dc + b * Dc + t];
    ctx[2 * Dc + t] = ebp[(size_t)a0 * Bc * Dc + b * Dc + t];
    __syncthreads();
    float s0 = 0.f, s1 = 0.f, s2 = 0.f, s3 = 0.f;
    #pragma unroll 4
    for (int i = 0; i < 3 * Dc; i += 4) {
        s0 = fmaf(ctx[i + 0], Wq1[(i + 0) * Dc + t], s0);
        s1 = fmaf(ctx[i + 1], Wq1[(i + 1) * Dc + t], s1);
        s2 = fmaf(ctx[i + 2], Wq1[(i + 2) * Dc + t], s2);
        s3 = fmaf(ctx[i + 3], Wq1[(i + 3) * Dc + t], s3);
    }
    g_q1[b * Dc + t] = (s0 + s1) + (s2 + s3);
}

// ---------------- qk[b,h,i] = sum_d q1[b,h*32+d] * Wk1[i,h*32+d] ----------------
__global__ void k_qk(const float* __restrict__ Wk1) {
    int bh = blockIdx.x;
    int b = bh >> 3, h = bh & 7;
    __shared__ float q1h[DHc];
    int t = threadIdx.x;
    if (t < DHc) q1h[t] = g_q1[b * Dc + h * DHc + t];
    __syncthreads();
    const float* wrow = Wk1 + t * Dc + h * DHc;
    float acc = 0.f;
    #pragma unroll
    for (int d = 0; d < DHc; d++) acc = fmaf(q1h[d], wrow[d], acc);
    g_qk[(b * Hc + h) * Dc + t] = acc * 0.17677669529663687f;  // 1/sqrt(32)
}

// ---------------- Pass 2: scores. grid (Bc, 4), 2-row pipeline, fold8 reduction ----------------
__global__ void __launch_bounds__(256, 2) k_scores(const float* __restrict__ ebp,
                                                   const int* __restrict__ pa) {
    int b = blockIdx.x, t = threadIdx.x;
    int warp = t >> 5, lane = t & 31;
    int l0 = blockIdx.y * 256;
    __shared__ unsigned mbits[32];
    if (t < 32) mbits[t] = 0u;
    __syncthreads();
    if (t < Tc) {
        int a = pa[b * Tc + t];
        atomicOr(&mbits[a >> 5], 1u << (a & 31));
    }
    __syncthreads();

    unsigned long long qkp[Hc][4];
    {
        const ulonglong2* qb = (const ulonglong2*)(g_qk + b * Hc * Dc);
        #pragma unroll
        for (int h = 0; h < Hc; h++) {
            ulonglong2 u0 = qb[h * (Dc / 4) + lane * 2];
            ulonglong2 u1 = qb[h * (Dc / 4) + lane * 2 + 1];
            qkp[h][0] = u0.x; qkp[h][1] = u0.y; qkp[h][2] = u1.x; qkp[h][3] = u1.y;
        }
    }

    int base = l0 + warp;     // rows: base + j*8, j=0..31
    ulonglong2 c0a, c0b, c1a, c1b;      // current 2 rows
    {
        const ulonglong2* p0 = (const ulonglong2*)(ebp + ((size_t)base * Bc + b) * Dc) + lane * 2;
        const ulonglong2* p1 = (const ulonglong2*)(ebp + ((size_t)(base + 8) * Bc + b) * Dc) + lane * 2;
        c0a = p0[0]; c0b = p0[1];
        c1a = p1[0]; c1b = p1[1];
    }
    #pragma unroll 4
    for (int j = 0; j < 32; j += 2) {
        ulonglong2 n0a, n0b, n1a, n1b;
        if (j + 2 < 32) {
            const ulonglong2* p0 = (const ulonglong2*)(ebp + ((size_t)(base + (j + 2) * 8) * Bc + b) * Dc) + lane * 2;
            const ulonglong2* p1 = (const ulonglong2*)(ebp + ((size_t)(base + (j + 3) * 8) * Bc + b) * Dc) + lane * 2;
            n0a = p0[0]; n0b = p0[1];
            n1a = p1[0]; n1b = p1[1];
        }
        unsigned long long e0[4] = {c0a.x, c0a.y, c0b.x, c0b.y};
        unsigned long long e1[4] = {c1a.x, c1a.y, c1b.x, c1b.y};
        float sc0[Hc], sc1[Hc];
        #pragma unroll
        for (int h = 0; h < Hc; h++) {
            unsigned long long acc0 = 0ull, acc1 = 0ull;
            #pragma unroll
            for (int e = 0; e < 4; e++) { fma2(acc0, e0[e], qkp[h][e]); fma2(acc1, e1[e], qkp[h][e]); }
            float2 f0 = ull2f2(acc0), f1 = ull2f2(acc1);
            sc0[h] = f0.x + f0.y;
            sc1[h] = f1.x + f1.y;
        }
        float v0 = fold8(sc0, lane);
        float v1 = fold8(sc1, lane);
        if ((lane & 3) == 0) {
            int h = lane >> 2;
            int la = base + j * 8, lb = la + 8;
            bool m0 = (mbits[la >> 5] >> (la & 31)) & 1u;
            bool m1 = (mbits[lb >> 5] >> (lb & 31)) & 1u;
            g_w[(b * Hc + h) * Lc + la] = m0 ? -1e30f : v0;
            g_w[(b * Hc + h) * Lc + lb] = m1 ? -1e30f : v1;
        }
        c0a = n0a; c0b = n0b; c1a = n1a; c1b = n1b;
    }
}

// ---------------- softmax over l for each (b,h), in place ----------------
__global__ void k_softmax_w() {
    int bh = blockIdx.x, t = threadIdx.x;
    float* row = g_w + bh * Lc;
    __shared__ float red[256];
    float v[4];
    float mx = -1e30f;
    #pragma unroll
    for (int i = 0; i < 4; i++) { v[i] = row[t + i * 256]; mx = fmaxf(mx, v[i]); }
    red[t] = mx; __syncthreads();
    for (int s = 128; s > 0; s >>= 1) { if (t < s) red[t] = fmaxf(red[t], red[t + s]); __syncthreads(); }
    mx = red[0]; __syncthreads();
    float sm = 0.f;
    #pragma unroll
    for (int i = 0; i < 4; i++) { v[i] = __expf(v[i] - mx); sm += v[i]; }
    red[t] = sm; __syncthreads();
    for (int s = 128; s > 0; s >>= 1) { if (t < s) red[t] += red[t + s]; __syncthreads(); }
    float inv = 1.0f / red[0];
    #pragma unroll
    for (int i = 0; i < 4; i++) row[t + i * 256] = v[i] * inv;
}

// ---------------- Pass 3: wE partials. grid (Bc, WE_CH), w-chunk staged in smem once ----------------
__global__ void __launch_bounds__(256) k_wE_part(const float* __restrict__ ebp) {
    int b = blockIdx.x, t = threadIdx.x;
    int cy = blockIdx.y;
    int lbase = cy * (Lc / WE_CH);     // 256-l chunk
    __shared__ float2 ws[Lc / WE_CH][4];   // 8KB: [ll][headpair]
    #pragma unroll
    for (int k = 0; k < 8; k++) {
        // h = k, ll = t
        float wv = g_w[(b * Hc + k) * Lc + lbase + t];
        ((float*)&ws[t][k >> 1])[k & 1] = wv;
    }
    __syncthreads();
    unsigned long long acc[4] = {0ull, 0ull, 0ull, 0ull};
    const float* col = ebp + (size_t)lbase * Bc * Dc + b * Dc + t;
    #pragma unroll 16
    for (int ll = 0; ll < Lc / WE_CH; ll++) {
        float e = col[(size_t)ll * Bc * Dc];
        unsigned long long ee = f2ull(e, e);
        ulonglong2 w01 = *(const ulonglong2*)&ws[ll][0];
        ulonglong2 w23 = *(const ulonglong2*)&ws[ll][2];
        fma2(acc[0], w01.x, ee);
        fma2(acc[1], w01.y, ee);
        fma2(acc[2], w23.x, ee);
        fma2(acc[3], w23.y, ee);
    }
    #pragma unroll
    for (int hp = 0; hp < 4; hp++) {
        float2 f = ull2f2(acc[hp]);
        g_wE_part[cy][(b * Hc + 2 * hp) * Dc + t]     = f.x;
        g_wE_part[cy][(b * Hc + 2 * hp + 1) * Dc + t] = f.y;
    }
}

// ---------------- fold chain: head_out -> context2 -> q2 -> qk2 (per b) ----------------
__global__ void k_fold(const float* __restrict__ Wv1, const float* __restrict__ Wo1,
                       const float* __restrict__ Wq2, const float* __restrict__ Wk2) {
    int b = blockIdx.x, t = threadIdx.x;
    __shared__ float wEs[Hc * Dc];
    __shared__ float hos[Hc * DHc];
    __shared__ float c2s[Dc];
    __shared__ float q2s[Dc];
    #pragma unroll
    for (int k = 0; k < Hc; k++) {
        float s = 0.f;
        #pragma unroll
        for (int c = 0; c < WE_CH; c++) s += g_wE_part[c][b * Hc * Dc + t + k * 256];
        wEs[t + k * 256] = s;
    }
    __syncthreads();
    {
        const float* wsrc = wEs + (t >> 5) * Dc;
        float s0 = 0.f, s1 = 0.f;
        #pragma unroll 4
        for (int i = 0; i < Dc; i += 2) {
            s0 = fmaf(wsrc[i],     Wv1[(i)     * Dc + t], s0);
            s1 = fmaf(wsrc[i + 1], Wv1[(i + 1) * Dc + t], s1);
        }
        hos[t] = s0 + s1;
    }
    __syncthreads();
    {
        float s0 = 0.f, s1 = 0.f;
        #pragma unroll 4
        for (int k = 0; k < Hc * DHc; k += 2) {
            s0 = fmaf(hos[k],     Wo1[(k)     * Dc + t], s0);
            s1 = fmaf(hos[k + 1], Wo1[(k + 1) * Dc + t], s1);
        }
        c2s[t] = s0 + s1;
    }
    __syncthreads();
    {
        float s0 = 0.f, s1 = 0.f;
        #pragma unroll 4
        for (int e = 0; e < Dc; e += 2) {
            s0 = fmaf(c2s[e],     Wq2[(e)     * Dc + t], s0);
            s1 = fmaf(c2s[e + 1], Wq2[(e + 1) * Dc + t], s1);
        }
        q2s[t] = s0 + s1;
    }
    __syncthreads();
    {
        const float* wr = Wk2 + t * Dc;
        float s0 = 0.f, s1 = 0.f;
        #pragma unroll 4
        for (int j = 0; j < Dc; j += 2) {
            s0 = fmaf(wr[j],     q2s[j],     s0);
            s1 = fmaf(wr[j + 1], q2s[j + 1], s1);
        }
        g_qk2[b * Dc + t] = (s0 + s1) * (1.0f / 16.0f);
    }
}

// ---------------- Pass 4a: fs. grid (Bc, 4), 4-row groups with prefetch, fold4 ----------------
__global__ void __launch_bounds__(256, 2) k_fs(const float* __restrict__ ebp,
                                               const int* __restrict__ pa) {
    int b = blockIdx.x, t = threadIdx.x;
    int warp = t >> 5, lane = t & 31;
    int l0 = blockIdx.y * 256;
    __shared__ unsigned mbits[32];
    if (t < 32) mbits[t] = 0u;
    __syncthreads();
    if (t < Tc) {
        int a = pa[b * Tc + t];
        atomicOr(&mbits[a >> 5], 1u << (a & 31));
    }
    __syncthreads();
    unsigned long long qp[4];
    {
        const ulonglong2* qb = (const ulonglong2*)(g_qk2 + b * Dc);
        ulonglong2 u0 = qb[lane * 2], u1 = qb[lane * 2 + 1];
        qp[0] = u0.x; qp[1] = u0.y; qp[2] = u1.x; qp[3] = u1.y;
    }
    int base = l0 + warp;   // rows base + j*8, j=0..31, groups of 4
    ulonglong2 cur[4][2], nxt[4][2];
    #pragma unroll
    for (int i = 0; i < 4; i++) {
        const ulonglong2* p = (const ulonglong2*)(ebp + ((size_t)(base + i * 8) * Bc + b) * Dc) + lane * 2;
        cur[i][0] = p[0]; cur[i][1] = p[1];
    }
    #pragma unroll 2
    for (int g = 0; g < 8; g++) {
        if (g < 7) {
            #pragma unroll
            for (int i = 0; i < 4; i++) {
                const ulonglong2* p = (const ulonglong2*)(ebp + ((size_t)(base + ((g + 1) * 4 + i) * 8) * Bc + b) * Dc) + lane * 2;
                nxt[i][0] = p[0]; nxt[i][1] = p[1];
            }
        }
        float r[4];
        #pragma unroll
        for (int i = 0; i < 4; i++) {
            unsigned long long acc = 0ull;
            fma2(acc, cur[i][0].x, qp[0]);
            fma2(acc, cur[i][0].y, qp[1]);
            fma2(acc, cur[i][1].x, qp[2]);
            fma2(acc, cur[i][1].y, qp[3]);
            float2 f = ull2f2(acc);
            r[i] = f.x + f.y;
        }
        float v = fold4(r, lane);
        if ((lane & 7) == 0) {
            int l = base + (g * 4 + (lane >> 3)) * 8;
            bool m = (mbits[l >> 5] >> (l & 31)) & 1u;
            g_fs[b * Lc + l] = m ? -1e30f : tanhf(v) * 10.0f;
        }
        #pragma unroll
        for (int i = 0; i < 4; i++) { cur[i][0] = nxt[i][0]; cur[i][1] = nxt[i][1]; }
    }
}

// ---------------- Pass 4b: per-b softmax over l, transposed store ----------------
__global__ void k_out(float* __restrict__ out) {
    int b = blockIdx.x, t = threadIdx.x;
    int warp = t >> 5, lane = t & 31;
    __shared__ float red[32];
    float v = g_fs[b * Lc + t];
    float mx = v;
    #pragma unroll
    for (int o = 16; o > 0; o >>= 1) mx = fmaxf(mx, __shfl_xor_sync(0xffffffffu, mx, o));
    if (lane == 0) red[warp] = mx;
    __syncthreads();
    if (t < 32) {
        float m = red[t];
        #pragma unroll
        for (int o = 16; o > 0; o >>= 1) m = fmaxf(m, __shfl_xor_sync(0xffffffffu, m, o));
        red[t] = m;
    }
    __syncthreads();
    mx = red[0];
    __syncthreads();
    float e = __expf(v - mx);
    float sm = e;
    #pragma unroll
    for (int o = 16; o > 0; o >>= 1) sm += __shfl_xor_sync(0xffffffffu, sm, o);
    if (lane == 0) red[warp] = sm;
    __syncthreads();
    if (t < 32) {
        float s = red[t];
        #pragma unroll
        for (int o = 16; o > 0; o >>= 1) s += __shfl_xor_sync(0xffffffffu, s, o);
        red[t] = s;
    }
    __syncthreads();
    out[(size_t)t * Bc + b] = e * (1.0f / red[0]);
}

extern "C" void kernel_launch(void* const* d_in, const int* in_sizes, int n_in,
                              void* d_out, int out_size) {
    const float* ebp = (const float*)d_in[0];
    const int*   pa  = (const int*)d_in[1];
    const float* Wq1 = (const float*)d_in[2];
    const float* Wk1 = (const float*)d_in[3];
    const float* Wv1 = (const float*)d_in[4];
    const float* Wo1 = (const float*)d_in[5];
    const float* Wq2 = (const float*)d_in[6];
    const float* Wk2 = (const float*)d_in[7];
    float* out = (float*)d_out;

    dim3 gm(64, MEAN_CH);
    k_mean_part<<<gm, 256>>>(ebp);
    k_q1       <<<Bc, 256>>>(ebp, pa, Wq1);
    k_qk       <<<Bc * Hc, 256>>>(Wk1);
    dim3 gs(Bc, 4);
    k_scores   <<<gs, 256>>>(ebp, pa);
    k_softmax_w<<<Bc * Hc, 256>>>();
    dim3 gw(Bc, WE_CH);
    k_wE_part  <<<gw, 256>>>(ebp);
    k_fold     <<<Bc, 256>>>(Wv1, Wo1, Wq2, Wk2);
    k_fs       <<<gs, 256>>>(ebp, pa);
    k_out      <<<Bc, 1024>>>(out);
}

// round 4
// speedup vs baseline: 1.4828x; 1.0206x over previous
#include <cuda_runtime.h>

#define Lc 1024
#define Bc 256
#define Dc 256
#define Tc 50
#define Hc 8
#define DHc 32

#define MEAN_CH 16  // L-chunks for mean pass
#define FL_CH 4     // L-chunks for flash pass

// Scratch (allocation-free rule: __device__ globals)
__device__ float g_hbar_part[MEAN_CH][Bc*Dc];
__device__ float g_q1[Bc*Dc];
__device__ float g_qk[Bc*Hc*Dc];                // [b][h][i], includes 1/sqrt(32)
__device__ float g_wE_part[FL_CH][Bc*Hc*Dc];    // unnormalized partial [b][h][i]
__device__ float2 g_ms[Bc*FL_CH*Hc];            // (m, s) per (b, chunk, h)
__device__ float g_qk2[Bc*Dc];                  // [b][i], includes 1/sqrt(256)
__device__ float g_fs[Bc*Lc];                   // [b][l]

__device__ __forceinline__ unsigned long long f2ull(float x, float y) {
    unsigned long long u;
    asm("mov.b64 %0, {%1,%2};" : "=l"(u) : "f"(x), "f"(y));
    return u;
}
__device__ __forceinline__ float2 ull2f2(unsigned long long u) {
    float2 f;
    asm("mov.b64 {%0,%1}, %2;" : "=f"(f.x), "=f"(f.y) : "l"(u));
    return f;
}
__device__ __forceinline__ void fma2(unsigned long long& acc, unsigned long long a, unsigned long long b) {
    asm("fma.rn.f32x2 %0, %1, %2, %3;" : "=l"(acc) : "l"(a), "l"(b), "l"(acc));
}
__device__ __forceinline__ void mul2(unsigned long long& a, unsigned long long b) {
    asm("mul.rn.f32x2 %0, %0, %1;" : "+l"(a) : "l"(b));
}

// 8-value fold reduction: lanes with lane%4==0 hold full sum for head (lane>>2). 9 shuffles.
__device__ __forceinline__ float fold8(const float sc[8], int lane) {
    bool hi16 = (lane & 16) != 0;
    float n[4];
    #pragma unroll
    for (int k = 0; k < 4; k++) {
        float give = hi16 ? sc[k] : sc[4 + k];
        float keep = hi16 ? sc[4 + k] : sc[k];
        n[k] = keep + __shfl_xor_sync(0xffffffffu, give, 16);
    }
    bool hi8 = (lane & 8) != 0;
    float m[2];
    #pragma unroll
    for (int j = 0; j < 2; j++) {
        float give = hi8 ? n[j] : n[2 + j];
        float keep = hi8 ? n[2 + j] : n[j];
        m[j] = keep + __shfl_xor_sync(0xffffffffu, give, 8);
    }
    bool hi4 = (lane & 4) != 0;
    float give = hi4 ? m[0] : m[1];
    float keep = hi4 ? m[1] : m[0];
    float v = keep + __shfl_xor_sync(0xffffffffu, give, 4);
    v += __shfl_xor_sync(0xffffffffu, v, 1);
    v += __shfl_xor_sync(0xffffffffu, v, 2);
    return v;
}

// 4-value fold: lanes with lane%8==0 hold row (lane>>3).
__device__ __forceinline__ float fold4(const float r[4], int lane) {
    bool hi16 = (lane & 16) != 0;
    float n[2];
    #pragma unroll
    for (int j = 0; j < 2; j++) {
        float give = hi16 ? r[j] : r[2 + j];
        float keep = hi16 ? r[2 + j] : r[j];
        n[j] = keep + __shfl_xor_sync(0xffffffffu, give, 16);
    }
    bool hi8 = (lane & 8) != 0;
    float give = hi8 ? n[0] : n[1];
    float keep = hi8 ? n[1] : n[0];
    float v = keep + __shfl_xor_sync(0xffffffffu, give, 8);
    v += __shfl_xor_sync(0xffffffffu, v, 4);
    v += __shfl_xor_sync(0xffffffffu, v, 2);
    v += __shfl_xor_sync(0xffffffffu, v, 1);
    return v;
}

// ---------------- Pass 1: partial sums for hbar. grid (64, MEAN_CH), block 256 ----------------
__global__ void k_mean_part(const float* __restrict__ ebp) {
    int cg = blockIdx.x * 256 + threadIdx.x;
    int l0 = blockIdx.y * (Lc / MEAN_CH);
    const float4* p = (const float4*)ebp + (size_t)l0 * (Bc * Dc / 4) + cg;
    float4 a0 = {0,0,0,0}, a1 = {0,0,0,0}, a2 = {0,0,0,0}, a3 = {0,0,0,0};
    #pragma unroll 2
    for (int l = 0; l < Lc / MEAN_CH; l += 8) {
        float4 v0 = p[(size_t)(l + 0) * (Bc * Dc / 4)];
        float4 v1 = p[(size_t)(l + 1) * (Bc * Dc / 4)];
        float4 v2 = p[(size_t)(l + 2) * (Bc * Dc / 4)];
        float4 v3 = p[(size_t)(l + 3) * (Bc * Dc / 4)];
        float4 v4 = p[(size_t)(l + 4) * (Bc * Dc / 4)];
        float4 v5 = p[(size_t)(l + 5) * (Bc * Dc / 4)];
        float4 v6 = p[(size_t)(l + 6) * (Bc * Dc / 4)];
        float4 v7 = p[(size_t)(l + 7) * (Bc * Dc / 4)];
        a0.x += v0.x; a0.y += v0.y; a0.z += v0.z; a0.w += v0.w;
        a1.x += v1.x; a1.y += v1.y; a1.z += v1.z; a1.w += v1.w;
        a2.x += v2.x; a2.y += v2.y; a2.z += v2.z; a2.w += v2.w;
        a3.x += v3.x; a3.y += v3.y; a3.z += v3.z; a3.w += v3.w;
        a0.x += v4.x; a0.y += v4.y; a0.z += v4.z; a0.w += v4.w;
        a1.x += v5.x; a1.y += v5.y; a1.z += v5.z; a1.w += v5.w;
        a2.x += v6.x; a2.y += v6.y; a2.z += v6.z; a2.w += v6.w;
        a3.x += v7.x; a3.y += v7.y; a3.z += v7.z; a3.w += v7.w;
    }
    float4 r;
    r.x = (a0.x + a1.x) + (a2.x + a3.x);
    r.y = (a0.y + a1.y) + (a2.y + a3.y);
    r.z = (a0.z + a1.z) + (a2.z + a3.z);
    r.w = (a0.w + a1.w) + (a2.w + a3.w);
    ((float4*)g_hbar_part[blockIdx.y])[cg] = r;
}

// ---------------- q1 = [hbar, prev_emb, first_emb] @ Wq1 ----------------
__global__ void k_q1(const float* __restrict__ ebp, const int* __restrict__ pa,
                     const float* __restrict__ Wq1) {
    int b = blockIdx.x, t = threadIdx.x;
    __shared__ float ctx[3 * Dc];
    int aL = pa[b * Tc + (Tc - 1)];
    int a0 = pa[b * Tc];
    float hs = 0.f;
    #pragma unroll
    for (int c = 0; c < MEAN_CH; c++) hs += g_hbar_part[c][b * Dc + t];
    ctx[t]          = hs * (1.0f / Lc);
    ctx[Dc + t]     = ebp[(size_t)aL * Bc * Dc + b * Dc + t];
    ctx[2 * Dc + t] = ebp[(size_t)a0 * Bc * Dc + b * Dc + t];
    __syncthreads();
    float s0 = 0.f, s1 = 0.f, s2 = 0.f, s3 = 0.f;
    #pragma unroll 4
    for (int i = 0; i < 3 * Dc; i += 4) {
        s0 = fmaf(ctx[i + 0], Wq1[(i + 0) * Dc + t], s0);
        s1 = fmaf(ctx[i + 1], Wq1[(i + 1) * Dc + t], s1);
        s2 = fmaf(ctx[i + 2], Wq1[(i + 2) * Dc + t], s2);
        s3 = fmaf(ctx[i + 3], Wq1[(i + 3) * Dc + t], s3);
    }
    g_q1[b * Dc + t] = (s0 + s1) + (s2 + s3);
}

// ---------------- qk[b,h,i] = sum_d q1[b,h*32+d] * Wk1[i,h*32+d] ----------------
__global__ void k_qk(const float* __restrict__ Wk1) {
    int bh = blockIdx.x;
    int b = bh >> 3, h = bh & 7;
    __shared__ float q1h[DHc];
    int t = threadIdx.x;
    if (t < DHc) q1h[t] = g_q1[b * Dc + h * DHc + t];
    __syncthreads();
    const float* wrow = Wk1 + t * Dc + h * DHc;
    float acc = 0.f;
    #pragma unroll
    for (int d = 0; d < DHc; d++) acc = fmaf(q1h[d], wrow[d], acc);
    g_qk[(b * Hc + h) * Dc + t] = acc * 0.17677669529663687f;  // 1/sqrt(32)
}

// ---------------- Fused pass: scores + online softmax + weighted-sum ----------------
// grid (Bc, FL_CH), block 256 (8 warps). 16-row tiles; warp w scores rows {2w, 2w+1};
// warp h owns head h's running (m, s); all threads accumulate acc[h][col=t].
__global__ void __launch_bounds__(256, 2) k_flash(const float* __restrict__ ebp,
                                                  const int* __restrict__ pa) {
    int b = blockIdx.x, t = threadIdx.x;
    int warp = t >> 5, lane = t & 31;
    int cy = blockIdx.y;
    int l0 = cy * 256;
    __shared__ float2 ws2[16][4];     // scores -> weights, packed head pairs
    __shared__ float fh[8];           // per-head rescale factor this tile
    __shared__ unsigned mbits[32];
    if (t < 32) mbits[t] = 0u;
    __syncthreads();
    if (t < Tc) {
        int a = pa[b * Tc + t];
        atomicOr(&mbits[a >> 5], 1u << (a & 31));
    }
    __syncthreads();

    unsigned long long qkp[Hc][4];
    {
        const ulonglong2* qb = (const ulonglong2*)(g_qk + b * Hc * Dc);
        #pragma unroll
        for (int h = 0; h < Hc; h++) {
            ulonglong2 u0 = qb[h * (Dc / 4) + lane * 2];
            ulonglong2 u1 = qb[h * (Dc / 4) + lane * 2 + 1];
            qkp[h][0] = u0.x; qkp[h][1] = u0.y; qkp[h][2] = u1.x; qkp[h][3] = u1.y;
        }
    }

    float m_run = -1e4f, s_run = 0.f;
    unsigned long long acc[4] = {0ull, 0ull, 0ull, 0ull};
    const float* colp = ebp + b * Dc + t;

    ulonglong2 cur[2][2], nxt[2][2];
    {
        const ulonglong2* p0 = (const ulonglong2*)(ebp + ((size_t)(l0 + warp * 2) * Bc + b) * Dc) + lane * 2;
        const ulonglong2* p1 = (const ulonglong2*)(ebp + ((size_t)(l0 + warp * 2 + 1) * Bc + b) * Dc) + lane * 2;
        cur[0][0] = p0[0]; cur[0][1] = p0[1];
        cur[1][0] = p1[0]; cur[1][1] = p1[1];
    }

    for (int tt = 0; tt < 16; tt++) {
        // ---- score phase: 2 rows per warp ----
        unsigned long long e0[4] = {cur[0][0].x, cur[0][0].y, cur[0][1].x, cur[0][1].y};
        unsigned long long e1[4] = {cur[1][0].x, cur[1][0].y, cur[1][1].x, cur[1][1].y};
        // prefetch next tile
        if (tt < 15) {
            int ln = l0 + (tt + 1) * 16 + warp * 2;
            const ulonglong2* p0 = (const ulonglong2*)(ebp + ((size_t)ln * Bc + b) * Dc) + lane * 2;
            const ulonglong2* p1 = (const ulonglong2*)(ebp + ((size_t)(ln + 1) * Bc + b) * Dc) + lane * 2;
            nxt[0][0] = p0[0]; nxt[0][1] = p0[1];
            nxt[1][0] = p1[0]; nxt[1][1] = p1[1];
        }
        float sc0[Hc], sc1[Hc];
        #pragma unroll
        for (int h = 0; h < Hc; h++) {
            unsigned long long a0 = 0ull, a1 = 0ull;
            #pragma unroll
            for (int e = 0; e < 4; e++) { fma2(a0, e0[e], qkp[h][e]); fma2(a1, e1[e], qkp[h][e]); }
            float2 f0 = ull2f2(a0), f1 = ull2f2(a1);
            sc0[h] = f0.x + f0.y;
            sc1[h] = f1.x + f1.y;
        }
        float v0 = fold8(sc0, lane);
        float v1 = fold8(sc1, lane);
        if ((lane & 3) == 0) {
            int h = lane >> 2;
            int la = l0 + tt * 16 + warp * 2, lb = la + 1;
            bool m0 = (mbits[la >> 5] >> (la & 31)) & 1u;
            bool m1 = (mbits[lb >> 5] >> (lb & 31)) & 1u;
            ((float*)&ws2[warp * 2][h >> 1])[h & 1]     = m0 ? -1e4f : v0;
            ((float*)&ws2[warp * 2 + 1][h >> 1])[h & 1] = m1 ? -1e4f : v1;
        }
        __syncthreads();

        // ---- online softmax update: warp `warp` owns head `warp` ----
        float scv = (lane < 16) ? ((float*)&ws2[lane][warp >> 1])[warp & 1] : -1e4f;
        float mt = scv;
        #pragma unroll
        for (int o = 16; o > 0; o >>= 1) mt = fmaxf(mt, __shfl_xor_sync(0xffffffffu, mt, o));
        float m_new = fmaxf(m_run, mt);
        float f = __expf(m_run - m_new);
        float wv = __expf(scv - m_new);
        float st = (lane < 16) ? wv : 0.f;
        #pragma unroll
        for (int o = 16; o > 0; o >>= 1) st += __shfl_xor_sync(0xffffffffu, st, o);
        s_run = s_run * f + st;
        m_run = m_new;
        if (lane < 16) ((float*)&ws2[lane][warp >> 1])[warp & 1] = wv;
        if (lane == 0) fh[warp] = f;
        __syncthreads();

        // ---- rescale + accumulate (rows re-read from L1) ----
        unsigned long long fp01 = f2ull(fh[0], fh[1]);
        unsigned long long fp23 = f2ull(fh[2], fh[3]);
        unsigned long long fp45 = f2ull(fh[4], fh[5]);
        unsigned long long fp67 = f2ull(fh[6], fh[7]);
        mul2(acc[0], fp01); mul2(acc[1], fp23);
        mul2(acc[2], fp45); mul2(acc[3], fp67);
        const float* cp = colp + (size_t)(l0 + tt * 16) * Bc * Dc;
        #pragma unroll
        for (int r = 0; r < 16; r++) {
            float e = cp[(size_t)r * Bc * Dc];
            unsigned long long ee = f2ull(e, e);
            ulonglong2 w01 = *(const ulonglong2*)&ws2[r][0];
            ulonglong2 w23 = *(const ulonglong2*)&ws2[r][2];
            fma2(acc[0], w01.x, ee);
            fma2(acc[1], w01.y, ee);
            fma2(acc[2], w23.x, ee);
            fma2(acc[3], w23.y, ee);
        }
        __syncthreads();
        cur[0][0] = nxt[0][0]; cur[0][1] = nxt[0][1];
        cur[1][0] = nxt[1][0]; cur[1][1] = nxt[1][1];
    }

    #pragma unroll
    for (int hp = 0; hp < 4; hp++) {
        float2 f2v = ull2f2(acc[hp]);
        g_wE_part[cy][(b * Hc + 2 * hp) * Dc + t]     = f2v.x;
        g_wE_part[cy][(b * Hc + 2 * hp + 1) * Dc + t] = f2v.y;
    }
    if (lane == 0) g_ms[(b * FL_CH + cy) * Hc + warp] = make_float2(m_run, s_run);
}

// ---------------- fold chain: combine chunks -> head_out -> context2 -> q2 -> qk2 ----------------
__global__ void k_fold(const float* __restrict__ Wv1, const float* __restrict__ Wo1,
                       const float* __restrict__ Wq2, const float* __restrict__ Wk2) {
    int b = blockIdx.x, t = threadIdx.x;
    __shared__ float wEs[Hc * Dc];
    __shared__ float hos[Hc * DHc];
    __shared__ float c2s[Dc];
    __shared__ float q2s[Dc];
    __shared__ float cf[FL_CH][Hc];
    if (t < Hc) {
        float2 ms[FL_CH];
        float M = -1e30f;
        #pragma unroll
        for (int c = 0; c < FL_CH; c++) {
            ms[c] = g_ms[(b * FL_CH + c) * Hc + t];
            M = fmaxf(M, ms[c].x);
        }
        float S = 0.f;
        float ef[FL_CH];
        #pragma unroll
        for (int c = 0; c < FL_CH; c++) {
            ef[c] = __expf(ms[c].x - M);
            S += ms[c].y * ef[c];
        }
        float invS = 1.0f / S;
        #pragma unroll
        for (int c = 0; c < FL_CH; c++) cf[c][t] = ef[c] * invS;
    }
    __syncthreads();
    #pragma unroll
    for (int h = 0; h < Hc; h++) {
        float s = 0.f;
        #pragma unroll
        for (int c = 0; c < FL_CH; c++)
            s += g_wE_part[c][(b * Hc + h) * Dc + t] * cf[c][h];
        wEs[h * Dc + t] = s;
    }
    __syncthreads();
    {
        const float* wsrc = wEs + (t >> 5) * Dc;
        float s0 = 0.f, s1 = 0.f;
        #pragma unroll 4
        for (int i = 0; i < Dc; i += 2) {
            s0 = fmaf(wsrc[i],     Wv1[(i)     * Dc + t], s0);
            s1 = fmaf(wsrc[i + 1], Wv1[(i + 1) * Dc + t], s1);
        }
        hos[t] = s0 + s1;
    }
    __syncthreads();
    {
        float s0 = 0.f, s1 = 0.f;
        #pragma unroll 4
        for (int k = 0; k < Hc * DHc; k += 2) {
            s0 = fmaf(hos[k],     Wo1[(k)     * Dc + t], s0);
            s1 = fmaf(hos[k + 1], Wo1[(k + 1) * Dc + t], s1);
        }
        c2s[t] = s0 + s1;
    }
    __syncthreads();
    {
        float s0 = 0.f, s1 = 0.f;
        #pragma unroll 4
        for (int e = 0; e < Dc; e += 2) {
            s0 = fmaf(c2s[e],     Wq2[(e)     * Dc + t], s0);
            s1 = fmaf(c2s[e + 1], Wq2[(e + 1) * Dc + t], s1);
        }
        q2s[t] = s0 + s1;
    }
    __syncthreads();
    {
        const float* wr = Wk2 + t * Dc;
        float s0 = 0.f, s1 = 0.f;
        #pragma unroll 4
        for (int j = 0; j < Dc; j += 2) {
            s0 = fmaf(wr[j],     q2s[j],     s0);
            s1 = fmaf(wr[j + 1], q2s[j + 1], s1);
        }
        g_qk2[b * Dc + t] = (s0 + s1) * (1.0f / 16.0f);
    }
}

// ---------------- Pass 4a: fs. grid (Bc, 4), 4-row groups with prefetch, fold4 ----------------
__global__ void __launch_bounds__(256, 2) k_fs(const float* __restrict__ ebp,
                                               const int* __restrict__ pa) {
    int b = blockIdx.x, t = threadIdx.x;
    int warp = t >> 5, lane = t & 31;
    int l0 = blockIdx.y * 256;
    __shared__ unsigned mbits[32];
    if (t < 32) mbits[t] = 0u;
    __syncthreads();
    if (t < Tc) {
        int a = pa[b * Tc + t];
        atomicOr(&mbits[a >> 5], 1u << (a & 31));
    }
    __syncthreads();
    unsigned long long qp[4];
    {
        const ulonglong2* qb = (const ulonglong2*)(g_qk2 + b * Dc);
        ulonglong2 u0 = qb[lane * 2], u1 = qb[lane * 2 + 1];
        qp[0] = u0.x; qp[1] = u0.y; qp[2] = u1.x; qp[3] = u1.y;
    }
    int base = l0 + warp;
    ulonglong2 cur[4][2], nxt[4][2];
    #pragma unroll
    for (int i = 0; i < 4; i++) {
        const ulonglong2* p = (const ulonglong2*)(ebp + ((size_t)(base + i * 8) * Bc + b) * Dc) + lane * 2;
        cur[i][0] = p[0]; cur[i][1] = p[1];
    }
    #pragma unroll 2
    for (int g = 0; g < 8; g++) {
        if (g < 7) {
            #pragma unroll
            for (int i = 0; i < 4; i++) {
                const ulonglong2* p = (const ulonglong2*)(ebp + ((size_t)(base + ((g + 1) * 4 + i) * 8) * Bc + b) * Dc) + lane * 2;
                nxt[i][0] = p[0]; nxt[i][1] = p[1];
            }
        }
        float r[4];
        #pragma unroll
        for (int i = 0; i < 4; i++) {
            unsigned long long acc = 0ull;
            fma2(acc, cur[i][0].x, qp[0]);
            fma2(acc, cur[i][0].y, qp[1]);
            fma2(acc, cur[i][1].x, qp[2]);
            fma2(acc, cur[i][1].y, qp[3]);
            float2 f = ull2f2(acc);
            r[i] = f.x + f.y;
        }
        float v = fold4(r, lane);
        if ((lane & 7) == 0) {
            int l = base + (g * 4 + (lane >> 3)) * 8;
            bool m = (mbits[l >> 5] >> (l & 31)) & 1u;
            g_fs[b * Lc + l] = m ? -1e30f : tanhf(v) * 10.0f;
        }
        #pragma unroll
        for (int i = 0; i < 4; i++) { cur[i][0] = nxt[i][0]; cur[i][1] = nxt[i][1]; }
    }
}

// ---------------- Pass 4b: per-b softmax over l (max is 10 by construction) ----------------
__global__ void k_out(float* __restrict__ out) {
    int b = blockIdx.x, t = threadIdx.x;
    int warp = t >> 5, lane = t & 31;
    __shared__ float red[32];
    float v = g_fs[b * Lc + t];
    float e = __expf(v - 10.0f);    // tanh*10 <= 10; mask -1e30 -> exp underflows to 0
    float sm = e;
    #pragma unroll
    for (int o = 16; o > 0; o >>= 1) sm += __shfl_xor_sync(0xffffffffu, sm, o);
    if (lane == 0) red[warp] = sm;
    __syncthreads();
    if (t < 32) {
        float s = red[t];
        #pragma unroll
        for (int o = 16; o > 0; o >>= 1) s += __shfl_xor_sync(0xffffffffu, s, o);
        red[t] = s;
    }
    __syncthreads();
    out[(size_t)t * Bc + b] = e * (1.0f / red[0]);
}

extern "C" void kernel_launch(void* const* d_in, const int* in_sizes, int n_in,
                              void* d_out, int out_size) {
    const float* ebp = (const float*)d_in[0];
    const int*   pa  = (const int*)d_in[1];
    const float* Wq1 = (const float*)d_in[2];
    const float* Wk1 = (const float*)d_in[3];
    const float* Wv1 = (const float*)d_in[4];
    const float* Wo1 = (const float*)d_in[5];
    const float* Wq2 = (const float*)d_in[6];
    const float* Wk2 = (const float*)d_in[7];
    float* out = (float*)d_out;

    dim3 gm(64, MEAN_CH);
    k_mean_part<<<gm, 256>>>(ebp);
    k_q1       <<<Bc, 256>>>(ebp, pa, Wq1);
    k_qk       <<<Bc * Hc, 256>>>(Wk1);
    dim3 gf(Bc, FL_CH);
    k_flash    <<<gf, 256>>>(ebp, pa);
    k_fold     <<<Bc, 256>>>(Wv1, Wo1, Wq2, Wk2);
    k_fs       <<<gf, 256>>>(ebp, pa);
    k_out      <<<Bc, 1024>>>(out);
}